// round 1
// baseline (speedup 1.0000x reference)
#include <cuda_runtime.h>
#include <cuda_bf16.h>

#define NLVL   4
#define BATCH  4
#define NBOX   128
#define MAXBS  64
#define CROP   14
#define CCH    256
#define NSLOTS (NLVL * BATCH * MAXBS)          // 1024
#define PTS    (CROP * CROP)                   // 196
#define C4     (CCH / 4)                       // 64 float4 per point
#define PG     (PTS / 4)                       // 49 point-groups of 4 per slot

// slot -> source box index (n in 0..127), or -1 if the slot is empty.
// Layout: [lvl][b][slot]
__device__ int g_slot_map[NSLOTS];

// ---------------------------------------------------------------------------
// Setup: per (batch, level) compute cumsum ranks over the 128 boxes, fill the
// slot map, and write the entire roi_boxes output (including zero slots).
// ---------------------------------------------------------------------------
__global__ void setup_kernel(const float* __restrict__ db, float* __restrict__ out_boxes) {
    int t = threadIdx.x;
    if (t >= BATCH * NLVL) return;
    int b   = t >> 2;
    int lvl = t & 3;
    float flvl = (float)lvl;

    int rank = 0;
    for (int n = 0; n < NBOX; ++n) {
        float id = db[(b * NBOX + n) * 7 + 0];
        if (id == flvl) {
            if (rank < MAXBS) {
                int slotIdx = (lvl * BATCH + b) * MAXBS + rank;
                g_slot_map[slotIdx] = n;
                float* ob = out_boxes + ((size_t)(b * NLVL + lvl) * MAXBS + rank) * 6;
                const float* src = db + (b * NBOX + n) * 7 + 1;
                #pragma unroll
                for (int k = 0; k < 6; ++k) ob[k] = src[k];
            }
            rank++;
        }
    }
    int filled = rank < MAXBS ? rank : MAXBS;
    for (int r = filled; r < MAXBS; ++r) {
        g_slot_map[(lvl * BATCH + b) * MAXBS + r] = -1;
        float* ob = out_boxes + ((size_t)(b * NLVL + lvl) * MAXBS + r) * 6;
        #pragma unroll
        for (int k = 0; k < 6; ++k) ob[k] = 0.0f;
    }
}

// ---------------------------------------------------------------------------
// Main: one block per (slot, group-of-4 grid points). 256 threads:
//   threadIdx/64 -> point within group, threadIdx%64 -> float4 channel group.
// Every output element is written exactly once.
// ---------------------------------------------------------------------------
__global__ void __launch_bounds__(256)
roi_kernel(const float* __restrict__ f0, const float* __restrict__ f1,
           const float* __restrict__ f2, const float* __restrict__ f3,
           const float* __restrict__ db, float* __restrict__ out) {
    int gid     = blockIdx.x;
    int slotIdx = gid / PG;
    int pg      = gid - slotIdx * PG;
    int point   = pg * 4 + (threadIdx.x >> 6);
    int c4      = threadIdx.x & 63;

    float4* outp = reinterpret_cast<float4*>(out)
                 + (size_t)slotIdx * (PTS * C4) + (size_t)point * C4 + c4;

    int n = g_slot_map[slotIdx];
    if (n < 0) { *outp = make_float4(0.f, 0.f, 0.f, 0.f); return; }

    int lvl = slotIdx >> 8;          // / (BATCH*MAXBS)
    int b   = (slotIdx >> 6) & 3;    // / MAXBS % BATCH
    int H   = 256 >> lvl;            // W == H per level

    const float* fm = (lvl == 0) ? f0 : (lvl == 1) ? f1 : (lvl == 2) ? f2 : f3;

    const float* bx = db + (b * NBOX + n) * 7;
    float cx = bx[1], cy = bx[2], w = bx[3], h = bx[4];

    // normalized box (image is 1024x1024 -> divide by 1023), same op order as ref
    float y1n = (cy - h * 0.5f) / 1023.0f;
    float y2n = (cy + h * 0.5f) / 1023.0f;
    float x1n = (cx - w * 0.5f) / 1023.0f;
    float x2n = (cx + w * 0.5f) / 1023.0f;

    float S = (float)(H - 1);
    int py = point / CROP;
    int px = point - py * CROP;
    float ty = (float)py * (1.0f / 13.0f);
    float tx = (float)px * (1.0f / 13.0f);

    float ys = y1n * S + ty * ((y2n - y1n) * S);
    float xs = x1n * S + tx * ((x2n - x1n) * S);

    // validity (sample outside image extent -> 0, matches ref extrapolation)
    if (!(ys >= 0.0f && ys <= S && xs >= 0.0f && xs <= S)) {
        *outp = make_float4(0.f, 0.f, 0.f, 0.f);
        return;
    }

    float y0f = floorf(ys), x0f = floorf(xs);
    float wy = ys - y0f;
    float wx = xs - x0f;

    int y0 = (int)y0f; y0 = y0 < 0 ? 0 : (y0 > H - 1 ? H - 1 : y0);
    int yb = y0 + 1;   yb = yb > H - 1 ? H - 1 : yb;
    int x0 = (int)x0f; x0 = x0 < 0 ? 0 : (x0 > H - 1 ? H - 1 : x0);
    int xb = x0 + 1;   xb = xb > H - 1 ? H - 1 : xb;

    const float4* fv = reinterpret_cast<const float4*>(fm);
    size_t rowT = ((size_t)b * H + y0) * H;   // in points
    size_t rowB = ((size_t)b * H + yb) * H;

    float4 v00 = __ldg(fv + (rowT + x0) * C4 + c4);
    float4 v01 = __ldg(fv + (rowT + xb) * C4 + c4);
    float4 v10 = __ldg(fv + (rowB + x0) * C4 + c4);
    float4 v11 = __ldg(fv + (rowB + xb) * C4 + c4);

    float ax = 1.0f - wx;
    float ay = 1.0f - wy;

    float4 r;
    r.x = (v00.x * ax + v01.x * wx) * ay + (v10.x * ax + v11.x * wx) * wy;
    r.y = (v00.y * ax + v01.y * wx) * ay + (v10.y * ax + v11.y * wx) * wy;
    r.z = (v00.z * ax + v01.z * wx) * ay + (v10.z * ax + v11.z * wx) * wy;
    r.w = (v00.w * ax + v01.w * wx) * ay + (v10.w * ax + v11.w * wx) * wy;

    *outp = r;
}

extern "C" void kernel_launch(void* const* d_in, const int* in_sizes, int n_in,
                              void* d_out, int out_size) {
    const float* f0 = (const float*)d_in[0];
    const float* f1 = (const float*)d_in[1];
    const float* f2 = (const float*)d_in[2];
    const float* f3 = (const float*)d_in[3];
    const float* db = (const float*)d_in[4];
    // d_in[5] = images: only the 1024x1024 shape matters (baked in as 1023).

    float* out = (float*)d_out;
    // Output layout: [4 lvl][4 B][64][14][14][256] fmaps, then [4 B][256][6] boxes
    float* out_boxes = out + (size_t)NSLOTS * PTS * CCH;

    setup_kernel<<<1, 32>>>(db, out_boxes);
    roi_kernel<<<NSLOTS * PG, 256>>>(f0, f1, f2, f3, db, out);
}

// round 2
// speedup vs baseline: 1.4902x; 1.4902x over previous
#include <cuda_runtime.h>
#include <cuda_bf16.h>

#define NLVL   4
#define BATCH  4
#define NBOX   128
#define MAXBS  64
#define CROP   14
#define CCH    256
#define NSLOTS (NLVL * BATCH * MAXBS)          // 1024
#define PTS    (CROP * CROP)                   // 196
#define C4     (CCH / 4)                       // 64 float4 per point
#define PG     (PTS / 4)                       // 49 point-groups of 4 per slot

// slot -> source box index (n in 0..127), or -1 if the slot is empty.
// Layout: [lvl][b][slot]
__device__ int g_slot_map[NSLOTS];

// ---------------------------------------------------------------------------
// Setup: 16 warps, one per (batch, level). Warp-ballot prefix scan over the
// 128 boxes (4 batches of 32) computes ranks in parallel; writes slot map and
// the full roi_boxes output (including zero slots).
// ---------------------------------------------------------------------------
__global__ void __launch_bounds__(512)
setup_kernel(const float* __restrict__ db, float* __restrict__ out_boxes) {
    int w    = threadIdx.x >> 5;
    int lane = threadIdx.x & 31;
    int b    = w >> 2;
    int lvl  = w & 3;
    float flvl = (float)lvl;

    int rank_base = 0;
    #pragma unroll
    for (int k = 0; k < 4; ++k) {
        int n = k * 32 + lane;
        float id = db[(b * NBOX + n) * 7 + 0];
        bool m = (id == flvl);
        unsigned mask = __ballot_sync(0xffffffffu, m);
        int rank = rank_base + __popc(mask & ((1u << lane) - 1u));
        if (m && rank < MAXBS) {
            g_slot_map[(lvl * BATCH + b) * MAXBS + rank] = n;
            float* ob = out_boxes + ((size_t)(b * NLVL + lvl) * MAXBS + rank) * 6;
            const float* src = db + (b * NBOX + n) * 7 + 1;
            #pragma unroll
            for (int q = 0; q < 6; ++q) ob[q] = src[q];
        }
        rank_base += __popc(mask);
    }
    int filled = rank_base < MAXBS ? rank_base : MAXBS;
    for (int r = filled + lane; r < MAXBS; r += 32) {
        g_slot_map[(lvl * BATCH + b) * MAXBS + r] = -1;
        float* ob = out_boxes + ((size_t)(b * NLVL + lvl) * MAXBS + r) * 6;
        #pragma unroll
        for (int q = 0; q < 6; ++q) ob[q] = 0.0f;
    }
}

// ---------------------------------------------------------------------------
// Main: one block per (slot, group-of-4 grid points). 256 threads:
//   threadIdx/64 -> point within group, threadIdx%64 -> float4 channel group.
// Threads 0..3 precompute the per-point corner offsets + weights into shared;
// all threads then gather 4 corners and lerp. Output stored once with .cs.
// ---------------------------------------------------------------------------
__global__ void __launch_bounds__(256)
roi_kernel(const float* __restrict__ f0, const float* __restrict__ f1,
           const float* __restrict__ f2, const float* __restrict__ f3,
           const float* __restrict__ db, float* __restrict__ out) {
    __shared__ int   s_o00[4], s_o01[4], s_o10[4], s_o11[4];  // float4-unit offsets
    __shared__ float s_wx[4], s_wy[4];
    __shared__ int   s_valid[4];

    int gid     = blockIdx.x;
    int slotIdx = gid / PG;
    int pg      = gid - slotIdx * PG;
    int pin     = threadIdx.x >> 6;           // point within group (0..3)
    int point   = pg * 4 + pin;
    int c4      = threadIdx.x & 63;

    float4* outp = reinterpret_cast<float4*>(out)
                 + (size_t)slotIdx * (PTS * C4) + (size_t)point * C4 + c4;

    int n = g_slot_map[slotIdx];              // uniform across block
    if (n < 0) {
        __stcs(outp, make_float4(0.f, 0.f, 0.f, 0.f));
        return;
    }

    int lvl = slotIdx >> 8;
    int H   = 256 >> lvl;

    if (threadIdx.x < 4) {
        int b = (slotIdx >> 6) & 3;
        const float* bx = db + (b * NBOX + n) * 7;
        float cx = bx[1], cy = bx[2], w = bx[3], h = bx[4];

        float y1n = (cy - h * 0.5f) / 1023.0f;
        float y2n = (cy + h * 0.5f) / 1023.0f;
        float x1n = (cx - w * 0.5f) / 1023.0f;
        float x2n = (cx + w * 0.5f) / 1023.0f;

        float S = (float)(H - 1);
        int pt  = pg * 4 + threadIdx.x;
        int py  = pt / CROP;
        int px  = pt - py * CROP;
        float ty = (float)py * (1.0f / 13.0f);
        float tx = (float)px * (1.0f / 13.0f);

        float ys = y1n * S + ty * ((y2n - y1n) * S);
        float xs = x1n * S + tx * ((x2n - x1n) * S);

        int valid = (ys >= 0.0f && ys <= S && xs >= 0.0f && xs <= S);
        s_valid[threadIdx.x] = valid;

        float y0f = floorf(ys), x0f = floorf(xs);
        s_wy[threadIdx.x] = ys - y0f;
        s_wx[threadIdx.x] = xs - x0f;

        int y0 = (int)y0f; y0 = y0 < 0 ? 0 : (y0 > H - 1 ? H - 1 : y0);
        int yb = y0 + 1;   yb = yb > H - 1 ? H - 1 : yb;
        int x0 = (int)x0f; x0 = x0 < 0 ? 0 : (x0 > H - 1 ? H - 1 : x0);
        int xb = x0 + 1;   xb = xb > H - 1 ? H - 1 : xb;

        int rowT = (b * H + y0) * H;
        int rowB = (b * H + yb) * H;
        s_o00[threadIdx.x] = (rowT + x0) * C4;
        s_o01[threadIdx.x] = (rowT + xb) * C4;
        s_o10[threadIdx.x] = (rowB + x0) * C4;
        s_o11[threadIdx.x] = (rowB + xb) * C4;
    }
    __syncthreads();

    if (!s_valid[pin]) {
        __stcs(outp, make_float4(0.f, 0.f, 0.f, 0.f));
        return;
    }

    const float* fm = (lvl == 0) ? f0 : (lvl == 1) ? f1 : (lvl == 2) ? f2 : f3;
    const float4* fv = reinterpret_cast<const float4*>(fm);

    float4 v00 = __ldg(fv + s_o00[pin] + c4);
    float4 v01 = __ldg(fv + s_o01[pin] + c4);
    float4 v10 = __ldg(fv + s_o10[pin] + c4);
    float4 v11 = __ldg(fv + s_o11[pin] + c4);

    float wx = s_wx[pin], wy = s_wy[pin];
    float ax = 1.0f - wx;
    float ay = 1.0f - wy;

    float4 r;
    r.x = (v00.x * ax + v01.x * wx) * ay + (v10.x * ax + v11.x * wx) * wy;
    r.y = (v00.y * ax + v01.y * wx) * ay + (v10.y * ax + v11.y * wx) * wy;
    r.z = (v00.z * ax + v01.z * wx) * ay + (v10.z * ax + v11.z * wx) * wy;
    r.w = (v00.w * ax + v01.w * wx) * ay + (v10.w * ax + v11.w * wx) * wy;

    __stcs(outp, r);
}

extern "C" void kernel_launch(void* const* d_in, const int* in_sizes, int n_in,
                              void* d_out, int out_size) {
    const float* f0 = (const float*)d_in[0];
    const float* f1 = (const float*)d_in[1];
    const float* f2 = (const float*)d_in[2];
    const float* f3 = (const float*)d_in[3];
    const float* db = (const float*)d_in[4];
    // d_in[5] = images: only the 1024x1024 shape matters (baked in as 1023).

    float* out = (float*)d_out;
    // Output layout: [4 lvl][4 B][64][14][14][256] fmaps, then [4 B][256][6] boxes
    float* out_boxes = out + (size_t)NSLOTS * PTS * CCH;

    setup_kernel<<<1, 512>>>(db, out_boxes);
    roi_kernel<<<NSLOTS * PG, 256>>>(f0, f1, f2, f3, db, out);
}